// round 14
// baseline (speedup 1.0000x reference)
#include <cuda_runtime.h>
#include <cuda_bf16.h>
#include <mma.h>
#include <cstdint>

// PINN 4-stream forward-mode dual eval via WMMA bf16 split-precision GEMMs.
// tcgen05 is rejected by this harness's ptxas target (sm_103 w/o 'a'); WMMA
// (sm_80 baseline) compiles fine and still engages the tensor pipe.
//
// Per 32-point tile: M = 128 rows (m = 4*pt + stream):
//   L1 (3->128)   scalar -> act1 (bf16 hi/lo, smem, ldm 136)
//   L2 (128->128) 3-split bf16 WMMA -> D f32 -> tanh epilogue -> act2 hi/lo
//   L3 (128->64)  3-split bf16 WMMA -> D f32 -> tanh epilogue fused with L4
//   L4 (64->1)    dot with W4 + cross-group reduce -> out [N,4] f32
// Split: v = hi + lo (bf16 each); D = Ah*Bh + Al*Bh + Ah*Bl.

using namespace nvcuda;

#define NPTS 32
#define THREADS 512

#define LDA 136   // bf16 act ldm (272B rows: conflict-free LDSM)
#define LDW2 136  // bf16 W2hi smem ldm
#define LDW3 72   // bf16 W3hi smem ldm (144B rows)
#define LDD 132   // f32 D ldm (528B rows)

// ---- smem offsets (bytes) ----
#define ACT_HI 0                    // 128*136*2 = 34816
#define ACT_LO 34816                // 34816
#define W2HI   69632                // 34816
#define W3HI   104448               // 18432
#define DBUF   122880               // 128*132*4 = 67584
#define SB2    190464               // 128 f32
#define SB3    190976               // 64 f32
#define SW4    191232               // 64 f32
#define SB4    191488               // 16B
#define PART   191504               // 32*4*16 f32 = 8192
#define SMEM_BYTES 199712

// lo-parts of weights live in global scratch (written by prep kernel)
__device__ __nv_bfloat16 gW2lo[128 * 128];
__device__ __nv_bfloat16 gW3lo[128 * 64];

__device__ __forceinline__ float tanh_fast(float x) {
    float y; asm("tanh.approx.f32 %0, %1;" : "=f"(y) : "f"(x)); return y;
}
__device__ __forceinline__ __nv_bfloat16 bfhi(float v) { return __float2bfloat16(v); }
__device__ __forceinline__ __nv_bfloat16 bflo(float v, __nv_bfloat16 h) {
    return __float2bfloat16(v - __bfloat162float(h));
}

__global__ void prep_kernel(const float* __restrict__ W2, const float* __restrict__ W3) {
    int i = blockIdx.x * blockDim.x + threadIdx.x;
    if (i < 128 * 128) {
        float v = W2[i];
        gW2lo[i] = bflo(v, bfhi(v));
    }
    if (i < 128 * 64) {
        float v = W3[i];
        gW3lo[i] = bflo(v, bfhi(v));
    }
}

__global__ __launch_bounds__(THREADS, 1)
void pinn_wmma_kernel(const float* __restrict__ x,
                      const float* __restrict__ W1, const float* __restrict__ b1,
                      const float* __restrict__ W2, const float* __restrict__ b2,
                      const float* __restrict__ W3, const float* __restrict__ b3,
                      const float* __restrict__ W4, const float* __restrict__ b4,
                      float* __restrict__ out, int n, int ntiles)
{
    extern __shared__ char smem[];
    __nv_bfloat16* actHi = (__nv_bfloat16*)(smem + ACT_HI);
    __nv_bfloat16* actLo = (__nv_bfloat16*)(smem + ACT_LO);
    __nv_bfloat16* w2hi  = (__nv_bfloat16*)(smem + W2HI);
    __nv_bfloat16* w3hi  = (__nv_bfloat16*)(smem + W3HI);
    float* D    = (float*)(smem + DBUF);
    float* sB2  = (float*)(smem + SB2);
    float* sB3  = (float*)(smem + SB3);
    float* sW4  = (float*)(smem + SW4);
    float* sB4  = (float*)(smem + SB4);
    float* part = (float*)(smem + PART);

    const int tid  = threadIdx.x;
    const int warp = tid >> 5;

    // ---- stage hi-weights (padded) + biases once; block is persistent ----
    for (int i = tid; i < 128 * 128; i += THREADS) {
        int k = i >> 7, nn = i & 127;
        w2hi[k * LDW2 + nn] = bfhi(W2[i]);
    }
    for (int i = tid; i < 128 * 64; i += THREADS) {
        int k = i >> 6, nn = i & 63;
        w3hi[k * LDW3 + nn] = bfhi(W3[i]);
    }
    if (tid < 128) sB2[tid] = b2[tid];
    if (tid < 64)  sB3[tid] = b3[tid];
    if (tid < 64)  sW4[tid] = W4[tid];
    if (tid == 0)  sB4[0]  = b4[0];
    __syncthreads();

    // warp tiling
    const int wm2 = (warp & 3) * 2;   // L2: m-tiles {wm2, wm2+1}
    const int wn2 = (warp >> 2) * 2;  // L2: n-tiles {wn2, wn2+1}
    const int mt3 = warp & 7;         // L3: m-tile
    const int nb3 = (warp >> 3) * 2;  // L3: n-tiles {nb3, nb3+1}

    for (int tile = blockIdx.x; tile < ntiles; tile += gridDim.x) {
        const int p0 = tile * NPTS;

        // ============ Layer 1: 3 -> 128 (scalar) ============
        #pragma unroll
        for (int j = 0; j < 8; ++j) {
            const int idx = tid + j * THREADS;       // 4096 = 32pt x 128n
            const int pt = idx >> 7, nn = idx & 127;
            int p = p0 + pt; if (p >= n) p = n - 1;
            const float xz = __ldg(&x[p * 3 + 0]);
            const float xt = __ldg(&x[p * 3 + 1]);
            const float xh = __ldg(&x[p * 3 + 2]);
            const float w0 = __ldg(&W1[nn]);
            const float w1 = __ldg(&W1[128 + nn]);
            const float w2 = __ldg(&W1[256 + nn]);
            const float u  = fmaf(w0, xz, fmaf(w1, xt, fmaf(w2, xh, __ldg(&b1[nn]))));
            const float h  = tanh_fast(u);
            const float d  = fmaf(-h, h, 1.0f);
            const float hz = d * w0;
            float v[4];
            v[0] = h; v[1] = hz; v[2] = d * w1; v[3] = -2.0f * h * w0 * hz;
            #pragma unroll
            for (int s = 0; s < 4; ++s) {
                const int m = pt * 4 + s;
                __nv_bfloat16 hb = bfhi(v[s]);
                actHi[m * LDA + nn] = hb;
                actLo[m * LDA + nn] = bflo(v[s], hb);
            }
        }
        __syncthreads();   // act1 ready

        // ============ Layer 2 WMMA: [128x128] = act1[128x128] @ W2 ============
        {
            wmma::fragment<wmma::accumulator, 16, 16, 16, float> acc[2][2];
            #pragma unroll
            for (int i = 0; i < 2; ++i)
                #pragma unroll
                for (int j2 = 0; j2 < 2; ++j2) wmma::fill_fragment(acc[i][j2], 0.0f);

            #pragma unroll
            for (int split = 0; split < 3; ++split) {
                const __nv_bfloat16* Ab = (split == 1) ? actLo : actHi;
                #pragma unroll
                for (int k = 0; k < 8; ++k) {
                    wmma::fragment<wmma::matrix_a, 16, 16, 16, __nv_bfloat16, wmma::row_major> a[2];
                    wmma::fragment<wmma::matrix_b, 16, 16, 16, __nv_bfloat16, wmma::row_major> b[2];
                    #pragma unroll
                    for (int i = 0; i < 2; ++i)
                        wmma::load_matrix_sync(a[i], Ab + (wm2 + i) * 16 * LDA + k * 16, LDA);
                    #pragma unroll
                    for (int j2 = 0; j2 < 2; ++j2) {
                        if (split == 2)
                            wmma::load_matrix_sync(b[j2], gW2lo + k * 16 * 128 + (wn2 + j2) * 16, 128);
                        else
                            wmma::load_matrix_sync(b[j2], w2hi + k * 16 * LDW2 + (wn2 + j2) * 16, LDW2);
                    }
                    #pragma unroll
                    for (int i = 0; i < 2; ++i)
                        #pragma unroll
                        for (int j2 = 0; j2 < 2; ++j2)
                            wmma::mma_sync(acc[i][j2], a[i], b[j2], acc[i][j2]);
                }
            }
            #pragma unroll
            for (int i = 0; i < 2; ++i)
                #pragma unroll
                for (int j2 = 0; j2 < 2; ++j2)
                    wmma::store_matrix_sync(D + (wm2 + i) * 16 * LDD + (wn2 + j2) * 16,
                                            acc[i][j2], LDD, wmma::mem_row_major);
        }
        __syncthreads();   // D2 ready; act1 reads done

        // ============ Layer 2 epilogue: tanh chain -> act2 hi/lo ============
        #pragma unroll
        for (int j = 0; j < 8; ++j) {
            const int idx = tid + j * THREADS;
            const int pt = idx >> 7, nn = idx & 127;
            const int mb = pt * 4;
            const float u   = D[(mb + 0) * LDD + nn] + sB2[nn];
            const float uz  = D[(mb + 1) * LDD + nn];
            const float ut  = D[(mb + 2) * LDD + nn];
            const float uzz = D[(mb + 3) * LDD + nn];
            const float h  = tanh_fast(u);
            const float d  = fmaf(-h, h, 1.0f);
            const float hz = d * uz;
            float v[4];
            v[0] = h; v[1] = hz; v[2] = d * ut;
            v[3] = fmaf(d, uzz, -2.0f * h * uz * hz);
            #pragma unroll
            for (int s = 0; s < 4; ++s) {
                const int m = mb + s;
                __nv_bfloat16 hb = bfhi(v[s]);
                actHi[m * LDA + nn] = hb;
                actLo[m * LDA + nn] = bflo(v[s], hb);
            }
        }
        __syncthreads();   // act2 ready; D2 reads done

        // ============ Layer 3 WMMA: [128x64] = act2[128x128] @ W3 ============
        {
            wmma::fragment<wmma::accumulator, 16, 16, 16, float> acc[2];
            wmma::fill_fragment(acc[0], 0.0f);
            wmma::fill_fragment(acc[1], 0.0f);

            #pragma unroll
            for (int split = 0; split < 3; ++split) {
                const __nv_bfloat16* Ab = (split == 1) ? actLo : actHi;
                #pragma unroll
                for (int k = 0; k < 8; ++k) {
                    wmma::fragment<wmma::matrix_a, 16, 16, 16, __nv_bfloat16, wmma::row_major> a;
                    wmma::fragment<wmma::matrix_b, 16, 16, 16, __nv_bfloat16, wmma::row_major> b[2];
                    wmma::load_matrix_sync(a, Ab + mt3 * 16 * LDA + k * 16, LDA);
                    #pragma unroll
                    for (int j2 = 0; j2 < 2; ++j2) {
                        if (split == 2)
                            wmma::load_matrix_sync(b[j2], gW3lo + k * 16 * 64 + (nb3 + j2) * 16, 64);
                        else
                            wmma::load_matrix_sync(b[j2], w3hi + k * 16 * LDW3 + (nb3 + j2) * 16, LDW3);
                    }
                    wmma::mma_sync(acc[0], a, b[0], acc[0]);
                    wmma::mma_sync(acc[1], a, b[1], acc[1]);
                }
            }
            wmma::store_matrix_sync(D + mt3 * 16 * LDD + (nb3 + 0) * 16, acc[0], LDD, wmma::mem_row_major);
            wmma::store_matrix_sync(D + mt3 * 16 * LDD + (nb3 + 1) * 16, acc[1], LDD, wmma::mem_row_major);
        }
        __syncthreads();   // D3 ready; act2 reads done

        // ============ Layer 3 epilogue + Layer 4 partial dot ============
        {
            const int pt = tid >> 4;          // 0..31
            const int grp = tid & 15;         // 4 neurons per group
            const int mb = pt * 4;
            float pv = 0.f, pz = 0.f, ptt = 0.f, pzz = 0.f;
            #pragma unroll
            for (int q = 0; q < 4; ++q) {
                const int nn = grp * 4 + q;
                const float u   = D[(mb + 0) * LDD + nn] + sB3[nn];
                const float uz  = D[(mb + 1) * LDD + nn];
                const float ut  = D[(mb + 2) * LDD + nn];
                const float uzz = D[(mb + 3) * LDD + nn];
                const float h  = tanh_fast(u);
                const float d  = fmaf(-h, h, 1.0f);
                const float hz = d * uz;
                const float w  = sW4[nn];
                pv  = fmaf(w, h, pv);
                pz  = fmaf(w, hz, pz);
                ptt = fmaf(w, d * ut, ptt);
                pzz = fmaf(w, fmaf(d, uzz, -2.0f * h * uz * hz), pzz);
            }
            part[(pt * 4 + 0) * 16 + grp] = pv;
            part[(pt * 4 + 1) * 16 + grp] = pz;
            part[(pt * 4 + 2) * 16 + grp] = ptt;
            part[(pt * 4 + 3) * 16 + grp] = pzz;
        }
        __syncthreads();
        if (tid < 128) {
            float t = 0.f;
            #pragma unroll
            for (int g = 0; g < 16; ++g) t += part[tid * 16 + g];
            if ((tid & 3) == 0) t += sB4[0];
            out[p0 * 4 + tid] = t;            // m = 4*pt + s maps directly
        }
        __syncthreads();   // protect D/part/act for next tile
    }
}

extern "C" void kernel_launch(void* const* d_in, const int* in_sizes, int n_in,
                              void* d_out, int out_size)
{
    const float* x  = (const float*)d_in[0];
    const float* W1 = (const float*)d_in[1];
    const float* b1 = (const float*)d_in[2];
    const float* W2 = (const float*)d_in[3];
    const float* b2 = (const float*)d_in[4];
    const float* W3 = (const float*)d_in[5];
    const float* b3 = (const float*)d_in[6];
    const float* W4 = (const float*)d_in[7];
    const float* b4 = (const float*)d_in[8];
    float* out = (float*)d_out;

    const int n = in_sizes[0] / 3;
    const int ntiles = (n + NPTS - 1) / NPTS;

    int sms = 148;
    (void)cudaDeviceGetAttribute(&sms, cudaDevAttrMultiProcessorCount, 0);
    (void)cudaFuncSetAttribute(pinn_wmma_kernel,
                               cudaFuncAttributeMaxDynamicSharedMemorySize, SMEM_BYTES);

    prep_kernel<<<(128 * 128 + 255) / 256, 256>>>(W2, W3);

    int grid = sms;
    if (grid > ntiles) grid = ntiles;
    pinn_wmma_kernel<<<grid, THREADS, SMEM_BYTES>>>(x, W1, b1, W2, b2, W3, b3, W4, b4,
                                                    out, n, ntiles);
}

// round 15
// speedup vs baseline: 1.9757x; 1.9757x over previous
#include <cuda_runtime.h>
#include <cuda_bf16.h>
#include <mma.h>
#include <cstdint>

// PINN 4-stream forward-mode dual eval via WMMA bf16 split-precision GEMMs.
// R14: all weight splits in smem (D aliases act via register-staged epilogue),
//      single-load k-loop (a_hi,a_lo,b_hi,b_lo -> 3 split MMAs), W1 in smem.
// Split: v = hi + lo (bf16 each); D = Ah*Bh + Al*Bh + Ah*Bl.

using namespace nvcuda;

#define NPTS 32
#define THREADS 512

#define LDA  136   // bf16 act ldm (272B rows, conflict-free LDSM)
#define LDW2 136   // bf16 W2 smem ldm
#define LDW3 72    // bf16 W3 smem ldm
#define LDD  132   // f32 D ldm (528B rows)

// ---- smem offsets (bytes) ----
// D (67584 B) aliases ACT_HI+ACT_LO (69632 B): epilogues register-stage.
#define ACT_HI 0                    // 34816
#define ACT_LO 34816                // 34816
#define DBUF   0                    // 67584 (alias)
#define W2HI   69632                // 34816
#define W2LO   104448               // 34816
#define W3HI   139264               // 18432
#define W3LO   157696               // 18432
#define SB2    176128               // 128 f32
#define SB3    176640               // 64 f32
#define SW4    176896               // 64 f32
#define SB4    177152               // 16 B
#define PART   177168               // 8192
#define SW1    185360               // 3*128 f32 = 1536
#define SB1    186896               // 128 f32 = 512
#define SMEM_BYTES 187408

__device__ __forceinline__ float tanh_fast(float x) {
    float y; asm("tanh.approx.f32 %0, %1;" : "=f"(y) : "f"(x)); return y;
}
__device__ __forceinline__ __nv_bfloat16 bfhi(float v) { return __float2bfloat16(v); }
__device__ __forceinline__ __nv_bfloat16 bflo(float v, __nv_bfloat16 h) {
    return __float2bfloat16(v - __bfloat162float(h));
}

__global__ __launch_bounds__(THREADS, 1)
void pinn_wmma_kernel(const float* __restrict__ x,
                      const float* __restrict__ W1, const float* __restrict__ b1,
                      const float* __restrict__ W2, const float* __restrict__ b2,
                      const float* __restrict__ W3, const float* __restrict__ b3,
                      const float* __restrict__ W4, const float* __restrict__ b4,
                      float* __restrict__ out, int n, int ntiles)
{
    extern __shared__ char smem[];
    __nv_bfloat16* actHi = (__nv_bfloat16*)(smem + ACT_HI);
    __nv_bfloat16* actLo = (__nv_bfloat16*)(smem + ACT_LO);
    __nv_bfloat16* w2hi  = (__nv_bfloat16*)(smem + W2HI);
    __nv_bfloat16* w2lo  = (__nv_bfloat16*)(smem + W2LO);
    __nv_bfloat16* w3hi  = (__nv_bfloat16*)(smem + W3HI);
    __nv_bfloat16* w3lo  = (__nv_bfloat16*)(smem + W3LO);
    float* D    = (float*)(smem + DBUF);
    float* sB2  = (float*)(smem + SB2);
    float* sB3  = (float*)(smem + SB3);
    float* sW4  = (float*)(smem + SW4);
    float* sB4  = (float*)(smem + SB4);
    float* part = (float*)(smem + PART);
    float* sW1  = (float*)(smem + SW1);
    float* sB1  = (float*)(smem + SB1);

    const int tid  = threadIdx.x;
    const int warp = tid >> 5;

    // ---- stage weights (hi+lo splits) + biases once; block is persistent ----
    for (int i = tid; i < 128 * 128; i += THREADS) {
        int k = i >> 7, nn = i & 127;
        float v = W2[i];
        __nv_bfloat16 h = bfhi(v);
        w2hi[k * LDW2 + nn] = h;
        w2lo[k * LDW2 + nn] = bflo(v, h);
    }
    for (int i = tid; i < 128 * 64; i += THREADS) {
        int k = i >> 6, nn = i & 63;
        float v = W3[i];
        __nv_bfloat16 h = bfhi(v);
        w3hi[k * LDW3 + nn] = h;
        w3lo[k * LDW3 + nn] = bflo(v, h);
    }
    if (tid < 3 * 128) sW1[tid] = W1[tid];
    if (tid < 128) sB1[tid] = b1[tid];
    if (tid < 128) sB2[tid] = b2[tid];
    if (tid < 64)  sB3[tid] = b3[tid];
    if (tid < 64)  sW4[tid] = W4[tid];
    if (tid == 0)  sB4[0]  = b4[0];
    __syncthreads();

    // warp tiling
    const int wm2 = (warp & 3) * 2;   // L2: m-tiles {wm2, wm2+1}
    const int wn2 = (warp >> 2) * 2;  // L2: n-tiles {wn2, wn2+1}
    const int mt3 = warp & 7;         // L3: m-tile
    const int nb3 = (warp >> 3) * 2;  // L3: n-tiles {nb3, nb3+1}

    for (int tile = blockIdx.x; tile < ntiles; tile += gridDim.x) {
        const int p0 = tile * NPTS;

        // ============ Layer 1: 3 -> 128 (scalar, W1 in smem) ============
        #pragma unroll
        for (int j = 0; j < 8; ++j) {
            const int idx = tid + j * THREADS;       // 4096 = 32pt x 128n
            const int pt = idx >> 7, nn = idx & 127;
            int p = p0 + pt; if (p >= n) p = n - 1;
            const float xz = __ldg(&x[p * 3 + 0]);
            const float xt = __ldg(&x[p * 3 + 1]);
            const float xh = __ldg(&x[p * 3 + 2]);
            const float w0 = sW1[nn];
            const float w1 = sW1[128 + nn];
            const float w2 = sW1[256 + nn];
            const float u  = fmaf(w0, xz, fmaf(w1, xt, fmaf(w2, xh, sB1[nn])));
            const float h  = tanh_fast(u);
            const float d  = fmaf(-h, h, 1.0f);
            const float hz = d * w0;
            float v[4];
            v[0] = h; v[1] = hz; v[2] = d * w1; v[3] = -2.0f * h * w0 * hz;
            #pragma unroll
            for (int s = 0; s < 4; ++s) {
                const int m = pt * 4 + s;
                __nv_bfloat16 hb = bfhi(v[s]);
                actHi[m * LDA + nn] = hb;
                actLo[m * LDA + nn] = bflo(v[s], hb);
            }
        }
        __syncthreads();   // act1 ready

        // ============ Layer 2 WMMA: D[128x128] = act1 @ W2 (3-split) ========
        {
            wmma::fragment<wmma::accumulator, 16, 16, 16, float> acc[2][2];
            #pragma unroll
            for (int i = 0; i < 2; ++i)
                #pragma unroll
                for (int j2 = 0; j2 < 2; ++j2) wmma::fill_fragment(acc[i][j2], 0.0f);

            #pragma unroll
            for (int k = 0; k < 8; ++k) {
                wmma::fragment<wmma::matrix_a, 16, 16, 16, __nv_bfloat16, wmma::row_major> aH[2], aL[2];
                wmma::fragment<wmma::matrix_b, 16, 16, 16, __nv_bfloat16, wmma::row_major> bH[2], bL[2];
                #pragma unroll
                for (int i = 0; i < 2; ++i) {
                    wmma::load_matrix_sync(aH[i], actHi + (wm2 + i) * 16 * LDA + k * 16, LDA);
                    wmma::load_matrix_sync(aL[i], actLo + (wm2 + i) * 16 * LDA + k * 16, LDA);
                }
                #pragma unroll
                for (int j2 = 0; j2 < 2; ++j2) {
                    wmma::load_matrix_sync(bH[j2], w2hi + k * 16 * LDW2 + (wn2 + j2) * 16, LDW2);
                    wmma::load_matrix_sync(bL[j2], w2lo + k * 16 * LDW2 + (wn2 + j2) * 16, LDW2);
                }
                #pragma unroll
                for (int i = 0; i < 2; ++i)
                    #pragma unroll
                    for (int j2 = 0; j2 < 2; ++j2) {
                        wmma::mma_sync(acc[i][j2], aH[i], bH[j2], acc[i][j2]);
                        wmma::mma_sync(acc[i][j2], aL[i], bH[j2], acc[i][j2]);
                        wmma::mma_sync(acc[i][j2], aH[i], bL[j2], acc[i][j2]);
                    }
            }
            __syncthreads();   // all act1 reads done (D aliases act)
            #pragma unroll
            for (int i = 0; i < 2; ++i)
                #pragma unroll
                for (int j2 = 0; j2 < 2; ++j2)
                    wmma::store_matrix_sync(D + (wm2 + i) * 16 * LDD + (wn2 + j2) * 16,
                                            acc[i][j2], LDD, wmma::mem_row_major);
        }
        __syncthreads();   // D2 ready

        // ===== Layer 2 epilogue (register-staged: D aliases act) =====
        {
            float st[8][4];
            #pragma unroll
            for (int j = 0; j < 8; ++j) {
                const int idx = tid + j * THREADS;
                const int pt = idx >> 7, nn = idx & 127;
                const int mb = pt * 4;
                st[j][0] = D[(mb + 0) * LDD + nn] + sB2[nn];
                st[j][1] = D[(mb + 1) * LDD + nn];
                st[j][2] = D[(mb + 2) * LDD + nn];
                st[j][3] = D[(mb + 3) * LDD + nn];
            }
            __syncthreads();   // all D reads done before act overwrite
            #pragma unroll
            for (int j = 0; j < 8; ++j) {
                const int idx = tid + j * THREADS;
                const int pt = idx >> 7, nn = idx & 127;
                const float u = st[j][0], uz = st[j][1], ut = st[j][2], uzz = st[j][3];
                const float h  = tanh_fast(u);
                const float d  = fmaf(-h, h, 1.0f);
                const float hz = d * uz;
                float v[4];
                v[0] = h; v[1] = hz; v[2] = d * ut;
                v[3] = fmaf(d, uzz, -2.0f * h * uz * hz);
                #pragma unroll
                for (int s = 0; s < 4; ++s) {
                    const int m = pt * 4 + s;
                    __nv_bfloat16 hb = bfhi(v[s]);
                    actHi[m * LDA + nn] = hb;
                    actLo[m * LDA + nn] = bflo(v[s], hb);
                }
            }
        }
        __syncthreads();   // act2 ready

        // ============ Layer 3 WMMA: D[128x64] = act2 @ W3 (3-split) =========
        {
            wmma::fragment<wmma::accumulator, 16, 16, 16, float> acc[2];
            wmma::fill_fragment(acc[0], 0.0f);
            wmma::fill_fragment(acc[1], 0.0f);

            #pragma unroll
            for (int k = 0; k < 8; ++k) {
                wmma::fragment<wmma::matrix_a, 16, 16, 16, __nv_bfloat16, wmma::row_major> aH, aL;
                wmma::fragment<wmma::matrix_b, 16, 16, 16, __nv_bfloat16, wmma::row_major> bH[2], bL[2];
                wmma::load_matrix_sync(aH, actHi + mt3 * 16 * LDA + k * 16, LDA);
                wmma::load_matrix_sync(aL, actLo + mt3 * 16 * LDA + k * 16, LDA);
                #pragma unroll
                for (int j2 = 0; j2 < 2; ++j2) {
                    wmma::load_matrix_sync(bH[j2], w3hi + k * 16 * LDW3 + (nb3 + j2) * 16, LDW3);
                    wmma::load_matrix_sync(bL[j2], w3lo + k * 16 * LDW3 + (nb3 + j2) * 16, LDW3);
                }
                #pragma unroll
                for (int j2 = 0; j2 < 2; ++j2) {
                    wmma::mma_sync(acc[j2], aH, bH[j2], acc[j2]);
                    wmma::mma_sync(acc[j2], aL, bH[j2], acc[j2]);
                    wmma::mma_sync(acc[j2], aH, bL[j2], acc[j2]);
                }
            }
            __syncthreads();   // all act2 reads done (D aliases act)
            wmma::store_matrix_sync(D + mt3 * 16 * LDD + (nb3 + 0) * 16, acc[0], LDD, wmma::mem_row_major);
            wmma::store_matrix_sync(D + mt3 * 16 * LDD + (nb3 + 1) * 16, acc[1], LDD, wmma::mem_row_major);
        }
        __syncthreads();   // D3 ready

        // ============ Layer 3 epilogue + Layer 4 partial dot ============
        {
            const int pt = tid >> 4;          // 0..31
            const int grp = tid & 15;         // 4 neurons per group
            const int mb = pt * 4;
            float pv = 0.f, pz = 0.f, ptt = 0.f, pzz = 0.f;
            #pragma unroll
            for (int q = 0; q < 4; ++q) {
                const int nn = grp * 4 + q;
                const float u   = D[(mb + 0) * LDD + nn] + sB3[nn];
                const float uz  = D[(mb + 1) * LDD + nn];
                const float ut  = D[(mb + 2) * LDD + nn];
                const float uzz = D[(mb + 3) * LDD + nn];
                const float h  = tanh_fast(u);
                const float d  = fmaf(-h, h, 1.0f);
                const float hz = d * uz;
                const float w  = sW4[nn];
                pv  = fmaf(w, h, pv);
                pz  = fmaf(w, hz, pz);
                ptt = fmaf(w, d * ut, ptt);
                pzz = fmaf(w, fmaf(d, uzz, -2.0f * h * uz * hz), pzz);
            }
            part[(pt * 4 + 0) * 16 + grp] = pv;
            part[(pt * 4 + 1) * 16 + grp] = pz;
            part[(pt * 4 + 2) * 16 + grp] = ptt;
            part[(pt * 4 + 3) * 16 + grp] = pzz;
        }
        __syncthreads();
        if (tid < 128) {
            float t = 0.f;
            #pragma unroll
            for (int g = 0; g < 16; ++g) t += part[tid * 16 + g];
            if ((tid & 3) == 0) t += sB4[0];
            if (p0 * 4 + tid < n * 4) out[p0 * 4 + tid] = t;  // m = 4*pt + s
        }
        __syncthreads();   // protect D/part/act for next tile
    }
}

extern "C" void kernel_launch(void* const* d_in, const int* in_sizes, int n_in,
                              void* d_out, int out_size)
{
    const float* x  = (const float*)d_in[0];
    const float* W1 = (const float*)d_in[1];
    const float* b1 = (const float*)d_in[2];
    const float* W2 = (const float*)d_in[3];
    const float* b2 = (const float*)d_in[4];
    const float* W3 = (const float*)d_in[5];
    const float* b3 = (const float*)d_in[6];
    const float* W4 = (const float*)d_in[7];
    const float* b4 = (const float*)d_in[8];
    float* out = (float*)d_out;

    const int n = in_sizes[0] / 3;
    const int ntiles = (n + NPTS - 1) / NPTS;

    int sms = 148;
    (void)cudaDeviceGetAttribute(&sms, cudaDevAttrMultiProcessorCount, 0);
    (void)cudaFuncSetAttribute(pinn_wmma_kernel,
                               cudaFuncAttributeMaxDynamicSharedMemorySize, SMEM_BYTES);

    int grid = sms;
    if (grid > ntiles) grid = ntiles;
    pinn_wmma_kernel<<<grid, THREADS, SMEM_BYTES>>>(x, W1, b1, W2, b2, W3, b3, W4, b4,
                                                    out, n, ntiles);
}